// round 1
// baseline (speedup 1.0000x reference)
#include <cuda_runtime.h>
#include <math.h>

// ---------------------------------------------------------------------------
// ASSR reconstruction loss, fully fused.
//   pix  = mean|pred - target|                 (32,3,512,512)
//   lr   = mean|bicubicAA_down4(pred) - lr_ref| (32,3,128,128)
//   out  = { pix + 0.1*lr, pix, lr, lr, 0 }
//
// Bicubic antialias (a=-0.75), scale=4, align_corners=False:
// center(o) = 4o + 1.5, taps j = 4o-6 .. 4o+9, dist = (j-center)/4 = (t-7.5)/4
//   -> identical 16-tap window for every output, window sum = 4.0 exactly.
// Border replicate folds clamped taps into columns 0 / 511 only.
// ---------------------------------------------------------------------------

#define HW       512
#define OUTHW    128
#define NBC      96            // 32 batch * 3 channels
#define RPS      16            // output rows per split (block)
#define SPLITS   (OUTHW / RPS) // 8
#define THREADS  512

// normalized taps (raw cubic values are dyadic; sum of raw = 4.0 exactly)
#define WT0 (-0.0025634765625f)
#define WT1 (-0.0164794921875f)
#define WT2 (-0.0274658203125f)
#define WT3 (-0.0179443359375f)
#define WT4 ( 0.0286865234375f)
#define WT5 ( 0.1065673828125f)
#define WT6 ( 0.1873779296875f)
#define WT7 ( 0.2418212890625f)
// border-folded sums (replicate clamp): WA = sum wt[0..6], WB = sum wt[0..2]
#define WA  ( 0.2581787109375f)
#define WB  (-0.0465087890625f)
#define WC  WB   // sum wt[13..15] (symmetry)
#define WD  WA   // sum wt[9..15]

__constant__ float c_wt[16] = {WT0,WT1,WT2,WT3,WT4,WT5,WT6,WT7,
                               WT7,WT6,WT5,WT4,WT3,WT2,WT1,WT0};

__device__ double g_pix_sum;
__device__ double g_lr_sum;

__global__ void zero_accum_kernel() {
    g_pix_sum = 0.0;
    g_lr_sum  = 0.0;
}

__global__ __launch_bounds__(THREADS)
void assr_fused_kernel(const float* __restrict__ pred,
                       const float* __restrict__ tgt,
                       const float* __restrict__ lrr)
{
    extern __shared__ float sh[];
    float* vrows = sh;                 // [RPS][512] vertical-resized rows
    float* red   = sh + RPS * HW;      // [32] reduction scratch

    const int w   = threadIdx.x;       // column 0..511
    const int s   = blockIdx.x;        // split 0..7
    const int bc  = blockIdx.y;        // 0..95
    const int oh0 = RPS * s;

    const float* P = pred + (size_t)bc * (HW * HW);
    const float* T = tgt  + (size_t)bc * (HW * HW);

    // ---------------- vertical polyphase FIR + pix reduction ---------------
    // Group k covers input rows h = 4k..4k+3, scattering into outputs
    // oh = k-2..k+2 with static per-phase tap patterns. A[i] <-> oh = k+(i-2).
    float A0 = 0.f, A1 = 0.f, A2 = 0.f, A3 = 0.f, A4 = 0.f;
    float pixs = 0.f;

    #pragma unroll
    for (int kk = 0; kk < RPS + 4; ++kk) {
        const int k  = oh0 - 2 + kk;
        const int hb = 4 * k;
        if (hb >= 0 && hb < HW) {
            const float* pp = P + (size_t)hb * HW + w;
            const float p0 = pp[0];
            const float p1 = pp[HW];
            const float p2 = pp[2 * HW];
            const float p3 = pp[3 * HW];
            if (kk >= 2 && kk < 2 + RPS) {   // core rows: count pix exactly once
                const float* tp = T + (size_t)hb * HW + w;
                pixs += fabsf(p0 - tp[0])      + fabsf(p1 - tp[HW])
                      + fabsf(p2 - tp[2 * HW]) + fabsf(p3 - tp[3 * HW]);
            }
            // phase r=0: taps 14,10,6,2 -> oh k-2..k+1
            if (hb == 0) { A2 += WA * p0; A3 += WB * p0; }   // border fold
            else { A0 += WT1 * p0; A1 += WT5 * p0; A2 += WT6 * p0; A3 += WT2 * p0; }
            // phase r=1: taps 15,11,7,3 -> oh k-2..k+1
            A0 += WT0 * p1; A1 += WT4 * p1; A2 += WT7 * p1; A3 += WT3 * p1;
            // phase r=2: taps 12,8,4,0  -> oh k-1..k+2
            A1 += WT3 * p2; A2 += WT7 * p2; A3 += WT4 * p2; A4 += WT0 * p2;
            // phase r=3: taps 13,9,5,1  -> oh k-1..k+2
            if (hb == HW - 4) { A1 += WC * p3; A2 += WD * p3; }  // border fold
            else { A1 += WT2 * p3; A2 += WT6 * p3; A3 += WT5 * p3; A4 += WT1 * p3; }
        }
        const int oh = k - 2;                 // A0 complete after group k
        if (oh >= oh0 && oh < oh0 + RPS)
            vrows[(oh - oh0) * HW + w] = A0;
        A0 = A1; A1 = A2; A2 = A3; A3 = A4; A4 = 0.f;
    }
    __syncthreads();

    // ---------------- horizontal FIR from smem + lr reduction --------------
    float lrs = 0.f;
    const int ow = w & (OUTHW - 1);
    const int r0 = w >> 7;                      // 0..3; rows r0, r0+4, ...
    const float* lrbase = lrr + (size_t)bc * (OUTHW * OUTHW)
                              + (size_t)oh0 * OUTHW + ow;

    if (ow >= 2 && ow < OUTHW - 2) {
        // interior: 5 aligned, conflict-free LDS.128 per output
        #pragma unroll
        for (int i = 0; i < RPS / 4; ++i) {
            const int rr = r0 + 4 * i;
            const float4* v =
                reinterpret_cast<const float4*>(vrows + rr * HW) + (ow - 2);
            const float4 a = v[0], b = v[1], c = v[2], d = v[3], e = v[4];
            float acc = a.z * WT0 + a.w * WT1
                      + b.x * WT2 + b.y * WT3 + b.z * WT4 + b.w * WT5
                      + c.x * WT6 + c.y * WT7 + c.z * WT7 + c.w * WT6
                      + d.x * WT5 + d.y * WT4 + d.z * WT3 + d.w * WT2
                      + e.x * WT1 + e.y * WT0;
            lrs += fabsf(acc - lrbase[rr * OUTHW]);
        }
    } else {
        // border ow in {0,1,126,127}: scalar clamped gather (replicate fold)
        for (int i = 0; i < RPS / 4; ++i) {
            const int rr = r0 + 4 * i;
            const float* row = vrows + rr * HW;
            float acc = 0.f;
            #pragma unroll
            for (int t = 0; t < 16; ++t) {
                int src = 4 * ow - 6 + t;
                src = src < 0 ? 0 : (src > HW - 1 ? HW - 1 : src);
                acc += c_wt[t] * row[src];
            }
            lrs += fabsf(acc - lrbase[rr * OUTHW]);
        }
    }

    // ---------------- block reduction + global double atomics --------------
    #pragma unroll
    for (int o = 16; o; o >>= 1) {
        pixs += __shfl_xor_sync(0xffffffffu, pixs, o);
        lrs  += __shfl_xor_sync(0xffffffffu, lrs,  o);
    }
    const int wid = w >> 5, lane = w & 31;
    if (lane == 0) { red[wid] = pixs; red[16 + wid] = lrs; }
    __syncthreads();
    if (w == 0) {
        double ps = 0.0, ls = 0.0;
        #pragma unroll
        for (int i = 0; i < 16; ++i) {
            ps += (double)red[i];
            ls += (double)red[16 + i];
        }
        atomicAdd(&g_pix_sum, ps);
        atomicAdd(&g_lr_sum, ls);
    }
}

__global__ void finalize_kernel(float* __restrict__ out, int out_size) {
    const double pix     = g_pix_sum / 25165824.0;   // 32*3*512*512
    const double lr      = g_lr_sum  / 1572864.0;    // 32*3*128*128
    const double consist = 1.0 * lr;                 // LAM_LR*lr + LAM_PAIR*0
    const double total   = pix + 0.1 * consist;      // LAM_CONSIST = 0.1
    float vals[5] = {(float)total, (float)pix, (float)consist, (float)lr, 0.f};
    for (int i = 0; i < out_size; ++i)
        out[i] = (i < 5) ? vals[i] : 0.f;
}

extern "C" void kernel_launch(void* const* d_in, const int* in_sizes, int n_in,
                              void* d_out, int out_size)
{
    const float* pred = (const float*)d_in[0];
    const float* tgt  = (const float*)d_in[1];
    const float* lrr  = (const float*)d_in[2];
    // d_in[3] (scale) is uniform 4.0 -> static sizes, unused.

    zero_accum_kernel<<<1, 1>>>();

    const dim3 grid(SPLITS, NBC);
    const size_t smem = (size_t)(RPS * HW + 32) * sizeof(float);  // 32,896 B
    assr_fused_kernel<<<grid, THREADS, smem>>>(pred, tgt, lrr);

    finalize_kernel<<<1, 1>>>((float*)d_out, out_size);
}